// round 2
// baseline (speedup 1.0000x reference)
#include <cuda_runtime.h>
#include <cstdint>

// Problem shape (fixed by the dataset)
#define CC    19
#define BATCH 8
#define HH    512
#define WW    512
#define HW    (HH * WW)          // 262144
#define NPIX  (BATCH * HW)       // 2097152

// Histogram-sort parameters
#define NBINS 131072             // 2^17 -> quantization error <= 3.8e-6 on the loss
#define CHUNK 2048
#define NCH   (NBINS / CHUNK)    // 64 chunks per class

// Static device scratch (no allocations allowed)
__device__ unsigned long long g_bins[CC * NBINS];   // low32 = count, high32 = fg count
__device__ unsigned long long g_chunk[CC * NCH];    // packed chunk totals
__device__ unsigned long long g_off[CC * NCH];      // packed exclusive offsets (descending order)
__device__ long long          g_gts[CC];
__device__ double             g_loss[CC];

// ---------------------------------------------------------------------------
// K0: zero bins + loss accumulators (required every call: graph is replayed)
// ---------------------------------------------------------------------------
__global__ void k_zero() {
    int i = blockIdx.x * blockDim.x + threadIdx.x;          // exactly CC*NBINS threads
    g_bins[i] = 0ULL;
    if (i < CC) g_loss[i] = 0.0;
}

// ---------------------------------------------------------------------------
// K1: fused softmax + error quantization + packed histogram scatter
// NOTE: target arrives as int32 (JAX demotes int64 with x64 disabled).
// ---------------------------------------------------------------------------
__global__ void k_scatter(const float* __restrict__ in, const int* __restrict__ tgt) {
    int t = blockIdx.x * blockDim.x + threadIdx.x;
    if (t >= NPIX) return;
    int b  = t / HW;
    int hw = t - b * HW;
    const float* base = in + (size_t)b * CC * HW + hw;

    float x[CC];
    float m = -1e30f;
#pragma unroll
    for (int c = 0; c < CC; c++) {
        x[c] = base[(size_t)c * HW];
        m = fmaxf(m, x[c]);
    }
    float s = 0.f;
#pragma unroll
    for (int c = 0; c < CC; c++) {
        x[c] = __expf(x[c] - m);
        s += x[c];
    }
    float inv = 1.0f / s;
    int lbl = tgt[t];

#pragma unroll
    for (int c = 0; c < CC; c++) {
        float p  = x[c] * inv;
        bool  fg = (c == lbl);
        float e  = fg ? (1.0f - p) : p;
        e = fmaxf(e, 0.0f);
        unsigned bin = (unsigned)(e * (float)NBINS);
        if (bin >= NBINS) bin = NBINS - 1;
        unsigned long long v = fg ? ((1ULL << 32) | 1ULL) : 1ULL;
        atomicAdd(&g_bins[c * NBINS + bin], v);
    }
}

// ---------------------------------------------------------------------------
// K2: per-(class, chunk) packed totals. Chunks are in DESCENDING bin order:
//     chunk ch covers global ranks [ch*CHUNK, (ch+1)*CHUNK), rank g -> bin NBINS-1-g
// ---------------------------------------------------------------------------
__global__ void k_chunkred() {
    int blk = blockIdx.x;            // c * NCH + ch
    int c   = blk / NCH;
    int ch  = blk - c * NCH;
    __shared__ unsigned long long sm[256];

    unsigned long long acc = 0;
    int gbase = ch * CHUNK;
    for (int q = threadIdx.x; q < CHUNK; q += 256) {
        int bin = NBINS - 1 - (gbase + q);
        acc += g_bins[c * NBINS + bin];
    }
    sm[threadIdx.x] = acc;
    __syncthreads();
    for (int d = 128; d > 0; d >>= 1) {
        if (threadIdx.x < d) sm[threadIdx.x] += sm[threadIdx.x + d];
        __syncthreads();
    }
    if (threadIdx.x == 0) g_chunk[blk] = sm[0];
}

// ---------------------------------------------------------------------------
// K3: tiny per-class exclusive scan over chunk totals (descending order) + gts
// ---------------------------------------------------------------------------
__global__ void k_scanchunks() {
    int c = threadIdx.x;
    if (c >= CC) return;
    unsigned long long run = 0;
    for (int ch = 0; ch < NCH; ch++) {
        g_off[c * NCH + ch] = run;
        run += g_chunk[c * NCH + ch];
    }
    g_gts[c] = (long long)(run >> 32);
}

// ---------------------------------------------------------------------------
// K4: ordered walk of each chunk (descending bins), Lovasz-Jaccard contribution
//     per nonempty bin:  e_bin * (jac(after) - jac(before)), double precision.
//     jac(n, f) = 1 - (gts - f) / (gts + n - f);  jac(0,0) == 0 automatically.
// ---------------------------------------------------------------------------
__global__ void k_loss() {
    const int T   = 256;
    const int PER = CHUNK / T;       // 8 bins per thread
    int blk = blockIdx.x;
    int c   = blk / NCH;
    int ch  = blk - c * NCH;
    int tid = threadIdx.x;

    long long gts = g_gts[c];
    if (gts == 0) return;            // class absent: excluded by 'present' mask
    double gtsd = (double)gts;

    unsigned long long mybins[PER];
    unsigned long long tsum = 0;
    int gbase = ch * CHUNK + tid * PER;
#pragma unroll
    for (int i = 0; i < PER; i++) {
        int bin = NBINS - 1 - (gbase + i);
        mybins[i] = g_bins[c * NBINS + bin];
        tsum += mybins[i];
    }

    // Hillis-Steele inclusive scan of per-thread packed sums
    __shared__ unsigned long long ssc[T];
    ssc[tid] = tsum;
    __syncthreads();
    for (int d = 1; d < T; d <<= 1) {
        unsigned long long v = (tid >= d) ? ssc[tid - d] : 0ULL;
        __syncthreads();
        ssc[tid] += v;
        __syncthreads();
    }
    unsigned long long run = (ssc[tid] - tsum) + g_off[c * NCH + ch];  // exclusive prefix

    double acc = 0.0;
#pragma unroll
    for (int i = 0; i < PER; i++) {
        unsigned long long v = mybins[i];
        if (v) {
            unsigned n0 = (unsigned)run;
            unsigned f0 = (unsigned)(run >> 32);
            unsigned long long run1 = run + v;
            unsigned n1 = (unsigned)run1;
            unsigned f1 = (unsigned)(run1 >> 32);
            int bin = NBINS - 1 - (gbase + i);
            double e  = ((double)bin + 0.5) * (1.0 / (double)NBINS);
            double j0 = 1.0 - (gtsd - (double)f0) / (gtsd + (double)n0 - (double)f0);
            double j1 = 1.0 - (gtsd - (double)f1) / (gtsd + (double)n1 - (double)f1);
            acc += e * (j1 - j0);
            run = run1;
        }
    }

    // block reduce (double) then one atomic per block
    __shared__ double sd[T];
    sd[tid] = acc;
    __syncthreads();
    for (int d = T / 2; d > 0; d >>= 1) {
        if (tid < d) sd[tid] += sd[tid + d];
        __syncthreads();
    }
    if (tid == 0) atomicAdd(&g_loss[c], sd[0]);
}

// ---------------------------------------------------------------------------
// K5: present-class average -> scalar output
// ---------------------------------------------------------------------------
__global__ void k_final(float* __restrict__ out) {
    if (threadIdx.x == 0) {
        double s = 0.0, np = 0.0;
        for (int c = 0; c < CC; c++) {
            if (g_gts[c] > 0) { s += g_loss[c]; np += 1.0; }
        }
        out[0] = (float)(s / (np > 1.0 ? np : 1.0));
    }
}

// ---------------------------------------------------------------------------
extern "C" void kernel_launch(void* const* d_in, const int* in_sizes, int n_in,
                              void* d_out, int out_size) {
    const float* input  = (const float*)d_in[0];
    const int*   target = (const int*)d_in[1];
    float*       out    = (float*)d_out;

    // CC*NBINS = 2,490,368 = 2432 * 1024
    k_zero<<<2432, 1024>>>();
    k_scatter<<<NPIX / 256, 256>>>(input, target);
    k_chunkred<<<CC * NCH, 256>>>();
    k_scanchunks<<<1, 32>>>();
    k_loss<<<CC * NCH, 256>>>();
    k_final<<<1, 32>>>(out);
}

// round 3
// speedup vs baseline: 1.2085x; 1.2085x over previous
#include <cuda_runtime.h>
#include <cstdint>

// Problem shape (fixed by the dataset)
#define CC    19
#define BATCH 8
#define HH    512
#define WW    512
#define HW    (HH * WW)          // 262144
#define NPIX  (BATCH * HW)       // 2097152

// Histogram-sort parameters.
// NBINS=16384: bin array = 19*16384*8B = 2.4 MB -> fully L2-resident under the
// 168 MB input stream. Loss quantization worst case = 0.5/NBINS ~ 3.1e-5 per
// class (Lovasz gradient sums to <= 1), 30x under the 1e-3 tolerance; measured
// error at 131072 bins was 6e-8, so expect ~1e-6 here.
#define NBINS 16384
#define CHUNK 2048
#define NCH   (NBINS / CHUNK)    // 8 chunks per class

// Static device scratch (no allocations allowed)
__device__ unsigned long long g_bins[CC * NBINS];   // low32 = count, high32 = fg count
__device__ unsigned long long g_chunk[CC * NCH];    // packed chunk totals
__device__ unsigned long long g_off[CC * NCH];      // packed exclusive offsets (descending order)
__device__ long long          g_gts[CC];
__device__ double             g_loss[CC];

// ---------------------------------------------------------------------------
// K0: zero bins + loss accumulators (required every call: graph is replayed)
// ---------------------------------------------------------------------------
__global__ void k_zero() {
    int i = blockIdx.x * blockDim.x + threadIdx.x;          // exactly CC*NBINS threads
    g_bins[i] = 0ULL;
    if (i < CC) g_loss[i] = 0.0;
}

// ---------------------------------------------------------------------------
// K1: fused softmax + error quantization + packed histogram scatter
// target arrives as int32 (JAX demotes int64 with x64 disabled).
// ---------------------------------------------------------------------------
__global__ void k_scatter(const float* __restrict__ in, const int* __restrict__ tgt) {
    int t = blockIdx.x * blockDim.x + threadIdx.x;
    if (t >= NPIX) return;
    int b  = t / HW;
    int hw = t - b * HW;
    const float* base = in + (size_t)b * CC * HW + hw;

    float x[CC];
    float m = -1e30f;
#pragma unroll
    for (int c = 0; c < CC; c++) {
        x[c] = base[(size_t)c * HW];
        m = fmaxf(m, x[c]);
    }
    float s = 0.f;
#pragma unroll
    for (int c = 0; c < CC; c++) {
        x[c] = __expf(x[c] - m);
        s += x[c];
    }
    float inv = 1.0f / s;
    int lbl = tgt[t];

#pragma unroll
    for (int c = 0; c < CC; c++) {
        float p  = x[c] * inv;
        bool  fg = (c == lbl);
        float e  = fg ? (1.0f - p) : p;
        e = fmaxf(e, 0.0f);
        unsigned bin = (unsigned)(e * (float)NBINS);
        if (bin >= NBINS) bin = NBINS - 1;
        unsigned long long v = fg ? ((1ULL << 32) | 1ULL) : 1ULL;
        atomicAdd(&g_bins[c * NBINS + bin], v);
    }
}

// ---------------------------------------------------------------------------
// K2: per-(class, chunk) packed totals. Chunks are in DESCENDING bin order:
//     chunk ch covers global ranks [ch*CHUNK, (ch+1)*CHUNK), rank g -> bin NBINS-1-g
// ---------------------------------------------------------------------------
__global__ void k_chunkred() {
    int blk = blockIdx.x;            // c * NCH + ch
    int c   = blk / NCH;
    int ch  = blk - c * NCH;
    __shared__ unsigned long long sm[256];

    unsigned long long acc = 0;
    int gbase = ch * CHUNK;
    for (int q = threadIdx.x; q < CHUNK; q += 256) {
        int bin = NBINS - 1 - (gbase + q);
        acc += g_bins[c * NBINS + bin];
    }
    sm[threadIdx.x] = acc;
    __syncthreads();
    for (int d = 128; d > 0; d >>= 1) {
        if (threadIdx.x < d) sm[threadIdx.x] += sm[threadIdx.x + d];
        __syncthreads();
    }
    if (threadIdx.x == 0) g_chunk[blk] = sm[0];
}

// ---------------------------------------------------------------------------
// K3: tiny per-class exclusive scan over chunk totals (descending order) + gts
// ---------------------------------------------------------------------------
__global__ void k_scanchunks() {
    int c = threadIdx.x;
    if (c >= CC) return;
    unsigned long long run = 0;
#pragma unroll
    for (int ch = 0; ch < NCH; ch++) {
        g_off[c * NCH + ch] = run;
        run += g_chunk[c * NCH + ch];
    }
    g_gts[c] = (long long)(run >> 32);
}

// ---------------------------------------------------------------------------
// K4: ordered walk of each chunk (descending bins), Lovasz-Jaccard contribution
//     per nonempty bin:  e_bin * (jac(after) - jac(before)), double precision.
//     jac(n, f) = 1 - (gts - f) / (gts + n - f);  jac(0,0) == 0 automatically.
// ---------------------------------------------------------------------------
__global__ void k_loss() {
    const int T   = 256;
    const int PER = CHUNK / T;       // 8 bins per thread
    int blk = blockIdx.x;
    int c   = blk / NCH;
    int ch  = blk - c * NCH;
    int tid = threadIdx.x;

    long long gts = g_gts[c];
    if (gts == 0) return;            // class absent: excluded by 'present' mask
    double gtsd = (double)gts;

    unsigned long long mybins[PER];
    unsigned long long tsum = 0;
    int gbase = ch * CHUNK + tid * PER;
#pragma unroll
    for (int i = 0; i < PER; i++) {
        int bin = NBINS - 1 - (gbase + i);
        mybins[i] = g_bins[c * NBINS + bin];
        tsum += mybins[i];
    }

    // Hillis-Steele inclusive scan of per-thread packed sums
    __shared__ unsigned long long ssc[T];
    ssc[tid] = tsum;
    __syncthreads();
    for (int d = 1; d < T; d <<= 1) {
        unsigned long long v = (tid >= d) ? ssc[tid - d] : 0ULL;
        __syncthreads();
        ssc[tid] += v;
        __syncthreads();
    }
    unsigned long long run = (ssc[tid] - tsum) + g_off[c * NCH + ch];  // exclusive prefix

    double acc = 0.0;
#pragma unroll
    for (int i = 0; i < PER; i++) {
        unsigned long long v = mybins[i];
        if (v) {
            unsigned n0 = (unsigned)run;
            unsigned f0 = (unsigned)(run >> 32);
            unsigned long long run1 = run + v;
            unsigned n1 = (unsigned)run1;
            unsigned f1 = (unsigned)(run1 >> 32);
            int bin = NBINS - 1 - (gbase + i);
            double e  = ((double)bin + 0.5) * (1.0 / (double)NBINS);
            double j0 = 1.0 - (gtsd - (double)f0) / (gtsd + (double)n0 - (double)f0);
            double j1 = 1.0 - (gtsd - (double)f1) / (gtsd + (double)n1 - (double)f1);
            acc += e * (j1 - j0);
            run = run1;
        }
    }

    // block reduce (double) then one atomic per block
    __shared__ double sd[T];
    sd[tid] = acc;
    __syncthreads();
    for (int d = T / 2; d > 0; d >>= 1) {
        if (tid < d) sd[tid] += sd[tid + d];
        __syncthreads();
    }
    if (tid == 0) atomicAdd(&g_loss[c], sd[0]);
}

// ---------------------------------------------------------------------------
// K5: present-class average -> scalar output
// ---------------------------------------------------------------------------
__global__ void k_final(float* __restrict__ out) {
    if (threadIdx.x == 0) {
        double s = 0.0, np = 0.0;
        for (int c = 0; c < CC; c++) {
            if (g_gts[c] > 0) { s += g_loss[c]; np += 1.0; }
        }
        out[0] = (float)(s / (np > 1.0 ? np : 1.0));
    }
}

// ---------------------------------------------------------------------------
extern "C" void kernel_launch(void* const* d_in, const int* in_sizes, int n_in,
                              void* d_out, int out_size) {
    const float* input  = (const float*)d_in[0];
    const int*   target = (const int*)d_in[1];
    float*       out    = (float*)d_out;

    // CC*NBINS = 311,296 = 304 * 1024
    k_zero<<<304, 1024>>>();
    k_scatter<<<NPIX / 256, 256>>>(input, target);
    k_chunkred<<<CC * NCH, 256>>>();
    k_scanchunks<<<1, 32>>>();
    k_loss<<<CC * NCH, 256>>>();
    k_final<<<1, 32>>>(out);
}

// round 4
// speedup vs baseline: 3.5230x; 2.9151x over previous
#include <cuda_runtime.h>
#include <cstdint>

// Problem shape (fixed by the dataset)
#define CC    19
#define BATCH 8
#define HH    512
#define WW    512
#define HW    (HH * WW)          // 262144
#define NPIX  (BATCH * HW)       // 2097152

// Histogram-sort: 2048 bins. Deterministic worst-case loss error =
// 0.5/NBINS * sum(lovasz grad)=1 -> 2.44e-4 << 1e-3 tolerance (measured ~1e-5).
#define NBINS 2048

#define SCAT_BLOCKS 148
#define SCAT_THREADS 512
#define SMEM_BYTES (CC * NBINS * 4)      // 155648 B count histogram

// Static device scratch (no allocations allowed)
__device__ unsigned int g_cnt[CC * NBINS];   // total error counts per (class, bin)
__device__ unsigned int g_fg[CC * NBINS];    // fg counts per (class, bin)
__device__ long long    g_gts[CC];
__device__ double       g_loss[CC];

// ---------------------------------------------------------------------------
// K0: zero global histograms (graph is replayed; must re-clear every call)
// ---------------------------------------------------------------------------
__global__ void k_zero() {
    int i = blockIdx.x * blockDim.x + threadIdx.x;
    if (i < CC * NBINS) { g_cnt[i] = 0u; g_fg[i] = 0u; }
}

// ---------------------------------------------------------------------------
// K1: fused softmax + error quantization + SMEM-privatized histogram.
// 148 persistent blocks; each privatizes the full 19x2048 count histogram in
// shared memory (atomicAdd on SMEM), then flushes nonzero bins to global with
// dense REDG. fg inserts (1 per pixel, 2M total) go straight to global.
// target arrives as int32 (JAX demotes int64 with x64 disabled).
// ---------------------------------------------------------------------------
__global__ void __launch_bounds__(SCAT_THREADS, 1)
k_scatter(const float* __restrict__ in, const int* __restrict__ tgt) {
    extern __shared__ unsigned int s_cnt[];          // [CC * NBINS]

    // init private histogram
    for (int i = threadIdx.x; i < CC * NBINS; i += SCAT_THREADS) s_cnt[i] = 0u;
    __syncthreads();

    const int stride = SCAT_BLOCKS * SCAT_THREADS;
    for (int t = blockIdx.x * SCAT_THREADS + threadIdx.x; t < NPIX; t += stride) {
        int b  = t >> 18;                 // t / HW
        int hw = t & (HW - 1);
        const float* base = in + (size_t)b * CC * HW + hw;

        float x[CC];
        float m = -1e30f;
#pragma unroll
        for (int c = 0; c < CC; c++) {
            x[c] = base[(size_t)c * HW];
            m = fmaxf(m, x[c]);
        }
        float s = 0.f;
#pragma unroll
        for (int c = 0; c < CC; c++) {
            x[c] = __expf(x[c] - m);
            s += x[c];
        }
        float inv = 1.0f / s;
        int lbl = tgt[t];

#pragma unroll
        for (int c = 0; c < CC; c++) {
            float p  = x[c] * inv;
            bool  fg = (c == lbl);
            float e  = fg ? (1.0f - p) : p;
            e = fmaxf(e, 0.0f);
            unsigned bin = (unsigned)(e * (float)NBINS);
            if (bin >= NBINS) bin = NBINS - 1;
            atomicAdd(&s_cnt[c * NBINS + bin], 1u);
            if (fg) atomicAdd(&g_fg[c * NBINS + bin], 1u);   // rare: 1 per pixel
        }
    }
    __syncthreads();

    // flush nonzero bins (dense, coalesced)
    for (int i = threadIdx.x; i < CC * NBINS; i += SCAT_THREADS) {
        unsigned v = s_cnt[i];
        if (v) atomicAdd(&g_cnt[i], v);
    }
}

// ---------------------------------------------------------------------------
// K2: one block per class. Scan packed (fg<<32 | cnt) over descending bins,
// derive gts from the scan total, then per-nonempty-bin Lovasz-Jaccard
// contribution: e_bin * (jac(after) - jac(before)) in double.
// jac(n, f) = 1 - (gts - f) / (gts + n - f); jac(0,0) == 0 automatically.
// ---------------------------------------------------------------------------
__global__ void k_loss() {
    const int T   = 256;
    const int PER = NBINS / T;           // 8 bins per thread
    int c   = blockIdx.x;
    int tid = threadIdx.x;

    unsigned long long mybins[PER];
    unsigned long long tsum = 0;
    int gbase = tid * PER;               // rank base; rank g -> bin NBINS-1-g
#pragma unroll
    for (int i = 0; i < PER; i++) {
        int bin = NBINS - 1 - (gbase + i);
        unsigned cnt = g_cnt[c * NBINS + bin];
        unsigned fg  = g_fg[c * NBINS + bin];
        mybins[i] = ((unsigned long long)fg << 32) | (unsigned long long)cnt;
        tsum += mybins[i];
    }

    // Hillis-Steele inclusive scan of per-thread packed sums
    __shared__ unsigned long long ssc[T];
    ssc[tid] = tsum;
    __syncthreads();
    for (int d = 1; d < T; d <<= 1) {
        unsigned long long v = (tid >= d) ? ssc[tid - d] : 0ULL;
        __syncthreads();
        ssc[tid] += v;
        __syncthreads();
    }
    unsigned long long total = ssc[T - 1];           // packed (gts<<32 | npix_class)
    long long gts = (long long)(total >> 32);
    unsigned long long run = ssc[tid] - tsum;        // exclusive prefix
    double gtsd = (double)gts;

    double acc = 0.0;
    if (gts > 0) {
#pragma unroll
        for (int i = 0; i < PER; i++) {
            unsigned long long v = mybins[i];
            if (v) {
                unsigned n0 = (unsigned)run;
                unsigned f0 = (unsigned)(run >> 32);
                unsigned long long run1 = run + v;
                unsigned n1 = (unsigned)run1;
                unsigned f1 = (unsigned)(run1 >> 32);
                int bin = NBINS - 1 - (gbase + i);
                double e  = ((double)bin + 0.5) * (1.0 / (double)NBINS);
                double j0 = 1.0 - (gtsd - (double)f0) / (gtsd + (double)n0 - (double)f0);
                double j1 = 1.0 - (gtsd - (double)f1) / (gtsd + (double)n1 - (double)f1);
                acc += e * (j1 - j0);
                run = run1;
            }
        }
    }

    // block reduce (double); one writer per class, no atomics
    __shared__ double sd[T];
    sd[tid] = acc;
    __syncthreads();
    for (int d = T / 2; d > 0; d >>= 1) {
        if (tid < d) sd[tid] += sd[tid + d];
        __syncthreads();
    }
    if (tid == 0) {
        g_loss[c] = sd[0];
        g_gts[c]  = gts;
    }
}

// ---------------------------------------------------------------------------
// K3: present-class average -> scalar output
// ---------------------------------------------------------------------------
__global__ void k_final(float* __restrict__ out) {
    if (threadIdx.x == 0) {
        double s = 0.0, np = 0.0;
        for (int c = 0; c < CC; c++) {
            if (g_gts[c] > 0) { s += g_loss[c]; np += 1.0; }
        }
        out[0] = (float)(s / (np > 1.0 ? np : 1.0));
    }
}

// ---------------------------------------------------------------------------
extern "C" void kernel_launch(void* const* d_in, const int* in_sizes, int n_in,
                              void* d_out, int out_size) {
    const float* input  = (const float*)d_in[0];
    const int*   target = (const int*)d_in[1];
    float*       out    = (float*)d_out;

    // Allow >48KB dynamic shared memory for the privatized histogram.
    // (Immediate API call, not stream-ordered: legal under graph capture.)
    cudaFuncSetAttribute(k_scatter, cudaFuncAttributeMaxDynamicSharedMemorySize,
                         SMEM_BYTES);

    k_zero<<<(CC * NBINS + 1023) / 1024, 1024>>>();
    k_scatter<<<SCAT_BLOCKS, SCAT_THREADS, SMEM_BYTES>>>(input, target);
    k_loss<<<CC, 256>>>();
    k_final<<<1, 32>>>(out);
}

// round 5
// speedup vs baseline: 3.7579x; 1.0667x over previous
#include <cuda_runtime.h>
#include <cstdint>

// Problem shape (fixed by the dataset)
#define CC    19
#define BATCH 8
#define HH    512
#define WW    512
#define HW    (HH * WW)          // 262144
#define NPIX  (BATCH * HW)       // 2097152

// Histogram-sort: 2048 bins. Deterministic worst-case loss error =
// 0.5/NBINS * sum(lovasz grad)=1 -> 2.44e-4 << 1e-3 tolerance (measured 1.3e-7).
#define NBINS 2048

#define SCAT_BLOCKS 148
#define SCAT_THREADS 1024
#define SMEM_BYTES (CC * NBINS * 4)      // 155648 B count histogram

// Static device scratch (no allocations allowed)
__device__ unsigned int g_cnt[CC * NBINS];   // total error counts per (class, bin)
__device__ unsigned int g_fg[CC * NBINS];    // fg counts per (class, bin)
__device__ long long    g_gts[CC];
__device__ double       g_loss[CC];
__device__ unsigned int g_ticket;

// ---------------------------------------------------------------------------
// K0: zero global histograms + ticket (graph replays; re-clear every call)
// ---------------------------------------------------------------------------
__global__ void k_zero() {
    int i = blockIdx.x * blockDim.x + threadIdx.x;
    if (i < CC * NBINS) { g_cnt[i] = 0u; g_fg[i] = 0u; }
    if (i == 0) g_ticket = 0u;
}

// ---------------------------------------------------------------------------
// K1: fused softmax + error quantization + SMEM-privatized histogram.
// 148 persistent blocks x 1024 threads (32 warps/SM for latency hiding);
// each block privatizes the full 19x2048 count histogram in shared memory,
// then flushes nonzero bins to global with dense REDG. fg inserts (1 per
// pixel, 2M total) go straight to global (low contention).
// target arrives as int32 (JAX demotes int64 with x64 disabled).
// ---------------------------------------------------------------------------
__global__ void __launch_bounds__(SCAT_THREADS, 1)
k_scatter(const float* __restrict__ in, const int* __restrict__ tgt) {
    extern __shared__ unsigned int s_cnt[];          // [CC * NBINS]

    // init private histogram
    for (int i = threadIdx.x; i < CC * NBINS; i += SCAT_THREADS) s_cnt[i] = 0u;
    __syncthreads();

    const int stride = SCAT_BLOCKS * SCAT_THREADS;
    for (int t = blockIdx.x * SCAT_THREADS + threadIdx.x; t < NPIX; t += stride) {
        int b  = t >> 18;                 // t / HW
        int hw = t & (HW - 1);
        const float* base = in + (size_t)b * CC * HW + hw;

        float x[CC];
        float m = -1e30f;
#pragma unroll
        for (int c = 0; c < CC; c++) {
            x[c] = base[(size_t)c * HW];
            m = fmaxf(m, x[c]);
        }
        float s = 0.f;
#pragma unroll
        for (int c = 0; c < CC; c++) {
            x[c] = __expf(x[c] - m);
            s += x[c];
        }
        float inv = 1.0f / s;
        int lbl = tgt[t];

#pragma unroll
        for (int c = 0; c < CC; c++) {
            float p  = x[c] * inv;
            bool  fg = (c == lbl);
            float e  = fg ? (1.0f - p) : p;
            e = fmaxf(e, 0.0f);
            unsigned bin = (unsigned)(e * (float)NBINS);
            if (bin >= NBINS) bin = NBINS - 1;
            atomicAdd(&s_cnt[c * NBINS + bin], 1u);
            if (fg) atomicAdd(&g_fg[c * NBINS + bin], 1u);   // rare: 1 per pixel
        }
    }
    __syncthreads();

    // flush nonzero bins (dense, coalesced)
    for (int i = threadIdx.x; i < CC * NBINS; i += SCAT_THREADS) {
        unsigned v = s_cnt[i];
        if (v) atomicAdd(&g_cnt[i], v);
    }
}

// ---------------------------------------------------------------------------
// K2: one block per class. Scan packed (fg<<32 | cnt) over descending bins,
// derive gts from the scan total, then per-nonempty-bin Lovasz-Jaccard
// contribution: e_bin * (jac(after) - jac(before)) in double.
// jac(n, f) = 1 - (gts - f) / (gts + n - f); jac(0,0) == 0 automatically.
// Last block (ticket) computes the present-class average -> scalar output.
// ---------------------------------------------------------------------------
__global__ void k_loss(float* __restrict__ out) {
    const int T   = 256;
    const int PER = NBINS / T;           // 8 bins per thread
    int c   = blockIdx.x;
    int tid = threadIdx.x;

    unsigned long long mybins[PER];
    unsigned long long tsum = 0;
    int gbase = tid * PER;               // rank base; rank g -> bin NBINS-1-g
#pragma unroll
    for (int i = 0; i < PER; i++) {
        int bin = NBINS - 1 - (gbase + i);
        unsigned cnt = g_cnt[c * NBINS + bin];
        unsigned fg  = g_fg[c * NBINS + bin];
        mybins[i] = ((unsigned long long)fg << 32) | (unsigned long long)cnt;
        tsum += mybins[i];
    }

    // Hillis-Steele inclusive scan of per-thread packed sums
    __shared__ unsigned long long ssc[T];
    ssc[tid] = tsum;
    __syncthreads();
    for (int d = 1; d < T; d <<= 1) {
        unsigned long long v = (tid >= d) ? ssc[tid - d] : 0ULL;
        __syncthreads();
        ssc[tid] += v;
        __syncthreads();
    }
    unsigned long long total = ssc[T - 1];           // packed (gts<<32 | npix_class)
    long long gts = (long long)(total >> 32);
    unsigned long long run = ssc[tid] - tsum;        // exclusive prefix
    double gtsd = (double)gts;

    double acc = 0.0;
    if (gts > 0) {
#pragma unroll
        for (int i = 0; i < PER; i++) {
            unsigned long long v = mybins[i];
            if (v) {
                unsigned n0 = (unsigned)run;
                unsigned f0 = (unsigned)(run >> 32);
                unsigned long long run1 = run + v;
                unsigned n1 = (unsigned)run1;
                unsigned f1 = (unsigned)(run1 >> 32);
                int bin = NBINS - 1 - (gbase + i);
                double e  = ((double)bin + 0.5) * (1.0 / (double)NBINS);
                double j0 = 1.0 - (gtsd - (double)f0) / (gtsd + (double)n0 - (double)f0);
                double j1 = 1.0 - (gtsd - (double)f1) / (gtsd + (double)n1 - (double)f1);
                acc += e * (j1 - j0);
                run = run1;
            }
        }
    }

    // block reduce (double); one writer per class
    __shared__ double sd[T];
    sd[tid] = acc;
    __syncthreads();
    for (int d = T / 2; d > 0; d >>= 1) {
        if (tid < d) sd[tid] += sd[tid + d];
        __syncthreads();
    }
    if (tid == 0) {
        g_loss[c] = sd[0];
        g_gts[c]  = gts;
        __threadfence();
        unsigned tk = atomicAdd(&g_ticket, 1u);
        if (tk == CC - 1) {                          // last class block finalizes
            __threadfence();
            double s = 0.0, np = 0.0;
            for (int k = 0; k < CC; k++) {
                if (g_gts[k] > 0) { s += g_loss[k]; np += 1.0; }
            }
            out[0] = (float)(s / (np > 1.0 ? np : 1.0));
        }
    }
}

// ---------------------------------------------------------------------------
extern "C" void kernel_launch(void* const* d_in, const int* in_sizes, int n_in,
                              void* d_out, int out_size) {
    const float* input  = (const float*)d_in[0];
    const int*   target = (const int*)d_in[1];
    float*       out    = (float*)d_out;

    // Allow >48KB dynamic shared memory for the privatized histogram.
    cudaFuncSetAttribute(k_scatter, cudaFuncAttributeMaxDynamicSharedMemorySize,
                         SMEM_BYTES);

    k_zero<<<(CC * NBINS + 1023) / 1024, 1024>>>();
    k_scatter<<<SCAT_BLOCKS, SCAT_THREADS, SMEM_BYTES>>>(input, target);
    k_loss<<<CC, 256>>>(out);
}